// round 2
// baseline (speedup 1.0000x reference)
#include <cuda_runtime.h>

// ---------------------------------------------------------------------------
// GCNEdgePredictorWithEmbeddings — round 1 baseline (fp32 SIMT)
//
// Math refactor (avoids materializing a_norm [8192x8192]):
//   w      = relu(attn)                          (applied on the fly)
//   deg[j] = sum_i w[i,j] ; dis = rsqrt(deg) (0 if deg<=0)
//   A_norm^T @ Y  ==  dis ⊙ ( w^T @ (dis ⊙ Y) )
// Pipeline:
//   deg_partial -> dis
//   P = dis ⊙ (emb[node_idx] @ W1)                      [8192,256]
//   H = relu( dis ⊙ (w^T @ P) + b1 )                    [8192,256]
//   Q = dis ⊙ (H @ W2)                                  [8192,128]
//   Z = dis ⊙ (w^T @ Q) + b2                            [8192,128]
//   scores[e] = dot(Z[src[e]], Z[dst[e]])               [2M]
// ---------------------------------------------------------------------------

static constexpr int N_NODES = 8192;
static constexpr int E_DIM_C = 256;
static constexpr int HID_C   = 256;
static constexpr int OUT_C   = 128;

// Scratch (device globals: no allocation at kernel_launch time)
__device__ float g_degp[64 * N_NODES];        // partial column sums
__device__ float g_dis [N_NODES];
__device__ float g_P   [N_NODES * HID_C];
__device__ float g_H   [N_NODES * HID_C];
__device__ float g_Q   [N_NODES * OUT_C];
__device__ float g_Z   [N_NODES * OUT_C];

// ---------------------------------------------------------------------------
// deg: two-phase deterministic column-sum of relu(attn)
// grid (8, 64), block 256; each thread: 4 columns (float4) x 128 rows
// ---------------------------------------------------------------------------
__global__ void deg_partial_kernel(const float* __restrict__ attn)
{
    int c4 = blockIdx.x * blockDim.x + threadIdx.x;   // float4 column index
    int r0 = blockIdx.y * 128;
    float4 s = make_float4(0.f, 0.f, 0.f, 0.f);
    const float4* a = reinterpret_cast<const float4*>(attn);
    #pragma unroll 4
    for (int r = 0; r < 128; ++r) {
        float4 v = a[(size_t)(r0 + r) * (N_NODES / 4) + c4];
        s.x += fmaxf(v.x, 0.f);
        s.y += fmaxf(v.y, 0.f);
        s.z += fmaxf(v.z, 0.f);
        s.w += fmaxf(v.w, 0.f);
    }
    reinterpret_cast<float4*>(g_degp)[blockIdx.y * (N_NODES / 4) + c4] = s;
}

__global__ void dis_kernel()
{
    int col = blockIdx.x * blockDim.x + threadIdx.x;
    float s = 0.f;
    #pragma unroll
    for (int r = 0; r < 64; ++r) s += g_degp[r * N_NODES + col];
    g_dis[col] = (s > 0.f) ? rsqrtf(s) : 0.f;
}

// ---------------------------------------------------------------------------
// Generic fp32 tiled GEMM:  C[M,N] = epi( rowScale[m] * sum_k Aop[k,m]*B[k,n] )
//   TRANS_A: A is [K, M] row-major (lda = M-stride). used for w^T @ Y.
//   !TRANS_A: A is [M, K] row-major (lda = K).
//   RELU_A: relu applied to A elements on load (attn -> w)
//   GATHER_A: A rows indirected through gatherIdx (embedding lookup)
//   epi: optional +bias[n], optional relu
// BM=128, BN=64, BK=16, TM=8, TN=4 -> 256 threads, register-prefetch pipeline
// ---------------------------------------------------------------------------
template<int BM, int BN, int BK, int TM, int TN,
         bool TRANS_A, bool RELU_A, bool GATHER_A,
         bool HAS_BIAS, bool RELU_OUT>
__global__ __launch_bounds__((BM / TM) * (BN / TN))
void gemm_kernel(const float* __restrict__ A, int lda,
                 const float* __restrict__ B,
                 float* __restrict__ C,
                 const float* __restrict__ bias,
                 const float* __restrict__ rowScale,
                 const int*   __restrict__ gatherIdx,
                 int M, int N, int K)
{
    constexpr int NT   = (BM / TM) * (BN / TN);     // 256
    constexpr int APAD = 4;
    constexpr int AV   = (BM * BK) / (4 * NT);      // float4 A loads / thread
    constexpr int BV   = (BK * BN) / (4 * NT);      // float4 B loads / thread

    __shared__ float As[BK][BM + APAD];
    __shared__ float Bs[BK][BN];

    const int tid = threadIdx.x;
    const int tx  = tid % (BN / TN);
    const int ty  = tid / (BN / TN);
    const int m0  = blockIdx.y * BM;
    const int n0  = blockIdx.x * BN;

    float4 areg[AV];
    float4 breg[BV];

    float acc[TM][TN];
    #pragma unroll
    for (int i = 0; i < TM; ++i)
        #pragma unroll
        for (int j = 0; j < TN; ++j) acc[i][j] = 0.f;

    auto loadA = [&](int k0) {
        #pragma unroll
        for (int v = 0; v < AV; ++v) {
            int idx = tid + v * NT;
            float4 t;
            if (TRANS_A) {
                int k  = idx / (BM / 4);
                int m4 = idx % (BM / 4);
                t = *reinterpret_cast<const float4*>(A + (size_t)(k0 + k) * lda + (m0 + m4 * 4));
            } else {
                int m  = idx / (BK / 4);
                int kq = idx % (BK / 4);
                int row;
                if (GATHER_A) row = gatherIdx[m0 + m];
                else          row = m0 + m;
                t = *reinterpret_cast<const float4*>(A + (size_t)row * lda + (k0 + kq * 4));
            }
            if (RELU_A) {
                t.x = fmaxf(t.x, 0.f); t.y = fmaxf(t.y, 0.f);
                t.z = fmaxf(t.z, 0.f); t.w = fmaxf(t.w, 0.f);
            }
            areg[v] = t;
        }
    };

    auto storeA = [&]() {
        #pragma unroll
        for (int v = 0; v < AV; ++v) {
            int idx = tid + v * NT;
            if (TRANS_A) {
                int k  = idx / (BM / 4);
                int m4 = idx % (BM / 4);
                *reinterpret_cast<float4*>(&As[k][m4 * 4]) = areg[v];
            } else {
                int m  = idx / (BK / 4);
                int kq = idx % (BK / 4);
                As[kq * 4 + 0][m] = areg[v].x;
                As[kq * 4 + 1][m] = areg[v].y;
                As[kq * 4 + 2][m] = areg[v].z;
                As[kq * 4 + 3][m] = areg[v].w;
            }
        }
    };

    auto loadB = [&](int k0) {
        #pragma unroll
        for (int v = 0; v < BV; ++v) {
            int idx = tid + v * NT;
            int k  = idx / (BN / 4);
            int n4 = idx % (BN / 4);
            breg[v] = *reinterpret_cast<const float4*>(B + (size_t)(k0 + k) * N + (n0 + n4 * 4));
        }
    };

    auto storeB = [&]() {
        #pragma unroll
        for (int v = 0; v < BV; ++v) {
            int idx = tid + v * NT;
            int k  = idx / (BN / 4);
            int n4 = idx % (BN / 4);
            *reinterpret_cast<float4*>(&Bs[k][n4 * 4]) = breg[v];
        }
    };

    loadA(0); loadB(0);
    storeA(); storeB();
    __syncthreads();

    const int KT = K / BK;
    for (int kt = 0; kt < KT; ++kt) {
        if (kt + 1 < KT) { loadA((kt + 1) * BK); loadB((kt + 1) * BK); }

        #pragma unroll
        for (int kk = 0; kk < BK; ++kk) {
            float a[TM], b[TN];
            #pragma unroll
            for (int i = 0; i < TM; i += 4) {
                float4 t = *reinterpret_cast<const float4*>(&As[kk][ty * TM + i]);
                a[i] = t.x; a[i + 1] = t.y; a[i + 2] = t.z; a[i + 3] = t.w;
            }
            #pragma unroll
            for (int j = 0; j < TN; j += 4) {
                float4 t = *reinterpret_cast<const float4*>(&Bs[kk][tx * TN + j]);
                b[j] = t.x; b[j + 1] = t.y; b[j + 2] = t.z; b[j + 3] = t.w;
            }
            #pragma unroll
            for (int i = 0; i < TM; ++i)
                #pragma unroll
                for (int j = 0; j < TN; ++j)
                    acc[i][j] = fmaf(a[i], b[j], acc[i][j]);
        }

        if (kt + 1 < KT) {
            __syncthreads();
            storeA(); storeB();
            __syncthreads();
        }
    }

    // epilogue: C = maybe_relu( rowScale[m]*acc + bias[n] )
    #pragma unroll
    for (int i = 0; i < TM; ++i) {
        int row = m0 + ty * TM + i;
        float sc = rowScale[row];
        #pragma unroll
        for (int j = 0; j < TN; j += 4) {
            int col = n0 + tx * TN + j;
            float4 r;
            r.x = acc[i][j + 0] * sc;
            r.y = acc[i][j + 1] * sc;
            r.z = acc[i][j + 2] * sc;
            r.w = acc[i][j + 3] * sc;
            if (HAS_BIAS) {
                float4 bb = *reinterpret_cast<const float4*>(bias + col);
                r.x += bb.x; r.y += bb.y; r.z += bb.z; r.w += bb.w;
            }
            if (RELU_OUT) {
                r.x = fmaxf(r.x, 0.f); r.y = fmaxf(r.y, 0.f);
                r.z = fmaxf(r.z, 0.f); r.w = fmaxf(r.w, 0.f);
            }
            *reinterpret_cast<float4*>(C + (size_t)row * N + col) = r;
        }
    }
}

// ---------------------------------------------------------------------------
// Edge decode: one warp per edge. Z rows are 128 floats = 32 lanes x float4.
// ---------------------------------------------------------------------------
__global__ void decode_kernel(const int* __restrict__ eli,
                              float* __restrict__ out, int nPred)
{
    int warp = (blockIdx.x * blockDim.x + threadIdx.x) >> 5;
    int lane = threadIdx.x & 31;
    if (warp >= nPred) return;
    int s = eli[warp];
    int d = eli[nPred + warp];
    const float4* zs = reinterpret_cast<const float4*>(g_Z + (size_t)s * OUT_C);
    const float4* zd = reinterpret_cast<const float4*>(g_Z + (size_t)d * OUT_C);
    float4 a = zs[lane];
    float4 b = zd[lane];
    float dot = a.x * b.x + a.y * b.y + a.z * b.z + a.w * b.w;
    #pragma unroll
    for (int o = 16; o; o >>= 1) dot += __shfl_xor_sync(0xffffffffu, dot, o);
    if (lane == 0) out[warp] = dot;
}

// ---------------------------------------------------------------------------
extern "C" void kernel_launch(void* const* d_in, const int* in_sizes, int n_in,
                              void* d_out, int out_size)
{
    const int*   nodeIdx = (const int*)  d_in[0];
    const float* attn    = (const float*)d_in[1];
    const int*   eli     = (const int*)  d_in[2];
    const float* emb     = (const float*)d_in[3];
    const float* W1      = (const float*)d_in[4];
    const float* b1      = (const float*)d_in[5];
    const float* W2      = (const float*)d_in[6];
    const float* b2      = (const float*)d_in[7];
    float* out = (float*)d_out;
    const int nPred = in_sizes[2] / 2;

    float *pDis, *pP, *pH, *pQ, *pZ;
    cudaGetSymbolAddress((void**)&pDis, g_dis);
    cudaGetSymbolAddress((void**)&pP,   g_P);
    cudaGetSymbolAddress((void**)&pH,   g_H);
    cudaGetSymbolAddress((void**)&pQ,   g_Q);
    cudaGetSymbolAddress((void**)&pZ,   g_Z);

    // 1) deg / dis
    deg_partial_kernel<<<dim3(N_NODES / (256 * 4), 64), 256>>>(attn);
    dis_kernel<<<N_NODES / 256, 256>>>();

    // 2) P = dis ⊙ (emb[nodeIdx] @ W1)      [8192,256] (NN, gather)
    gemm_kernel<128, 64, 16, 8, 4, false, false, true, false, false>
        <<<dim3(HID_C / 64, N_NODES / 128), 256>>>(
            emb, E_DIM_C, W1, pP, nullptr, pDis, nodeIdx,
            N_NODES, HID_C, E_DIM_C);

    // 3) H = relu( dis ⊙ (relu(attn)^T @ P) + b1 )   [8192,256] (TN)
    gemm_kernel<128, 64, 16, 8, 4, true, true, false, true, true>
        <<<dim3(HID_C / 64, N_NODES / 128), 256>>>(
            attn, N_NODES, pP, pH, b1, pDis, nullptr,
            N_NODES, HID_C, N_NODES);

    // 4) Q = dis ⊙ (H @ W2)                  [8192,128] (NN)
    gemm_kernel<128, 64, 16, 8, 4, false, false, false, false, false>
        <<<dim3(OUT_C / 64, N_NODES / 128), 256>>>(
            pH, HID_C, W2, pQ, nullptr, pDis, nullptr,
            N_NODES, OUT_C, HID_C);

    // 5) Z = dis ⊙ (relu(attn)^T @ Q) + b2   [8192,128] (TN)
    gemm_kernel<128, 64, 16, 8, 4, true, true, false, true, false>
        <<<dim3(OUT_C / 64, N_NODES / 128), 256>>>(
            attn, N_NODES, pQ, pZ, b2, pDis, nullptr,
            N_NODES, OUT_C, N_NODES);

    // 6) decode: warp per edge
    {
        int warpsPerBlock = 8;                      // 256 threads
        int blocks = (nPred + warpsPerBlock - 1) / warpsPerBlock;
        decode_kernel<<<blocks, 256>>>(eli, out, nPred);
    }
}

// round 3
// speedup vs baseline: 1.1051x; 1.1051x over previous
#include <cuda_runtime.h>

// ---------------------------------------------------------------------------
// GCNEdgePredictorWithEmbeddings — round 2: FFMA2 (fp32x2) SIMT GEMM + split-K
//
//   w      = relu(attn)   (on the fly)
//   deg[j] = sum_i w[i,j] ; dis = rsqrt(deg) (0 if deg<=0)
//   A_norm^T @ Y  ==  dis ⊙ ( w^T @ (dis ⊙ Y) )
// Pipeline:
//   P = dis ⊙ (emb[node_idx] @ W1)
//   H = relu( dis ⊙ (w^T @ P) + b1 )
//   Q = dis ⊙ (H @ W2)
//   Z = dis ⊙ (w^T @ Q) + b2        (split-K=2 + reduce)
//   scores[e] = dot(Z[src], Z[dst])
// ---------------------------------------------------------------------------

static constexpr int N_NODES = 8192;
static constexpr int E_DIM_C = 256;
static constexpr int HID_C   = 256;
static constexpr int OUT_C   = 128;
static constexpr int SPLITK_Z = 2;

__device__ float g_degp[64 * N_NODES];
__device__ float g_dis [N_NODES];
__device__ float g_P   [N_NODES * HID_C];
__device__ float g_H   [N_NODES * HID_C];
__device__ float g_Q   [N_NODES * OUT_C];
__device__ float g_Z   [N_NODES * OUT_C];
__device__ float g_part[SPLITK_Z * N_NODES * OUT_C];

// ---------------------------------------------------------------------------
__global__ void deg_partial_kernel(const float* __restrict__ attn)
{
    int c4 = blockIdx.x * blockDim.x + threadIdx.x;
    int r0 = blockIdx.y * 128;
    float4 s = make_float4(0.f, 0.f, 0.f, 0.f);
    const float4* a = reinterpret_cast<const float4*>(attn);
    #pragma unroll 4
    for (int r = 0; r < 128; ++r) {
        float4 v = a[(size_t)(r0 + r) * (N_NODES / 4) + c4];
        s.x += fmaxf(v.x, 0.f);
        s.y += fmaxf(v.y, 0.f);
        s.z += fmaxf(v.z, 0.f);
        s.w += fmaxf(v.w, 0.f);
    }
    reinterpret_cast<float4*>(g_degp)[blockIdx.y * (N_NODES / 4) + c4] = s;
}

__global__ void dis_kernel()
{
    int col = blockIdx.x * blockDim.x + threadIdx.x;
    float s = 0.f;
    #pragma unroll
    for (int r = 0; r < 64; ++r) s += g_degp[r * N_NODES + col];
    g_dis[col] = (s > 0.f) ? rsqrtf(s) : 0.f;
}

// ---------------------------------------------------------------------------
// fp32x2-packed tiled GEMM.
//   C[M,N] = epi( rowScale[m] * sum_k Aop[k,m]*B[k,n] )
// BM=128, BN=64, BK=16, TM=8, TN=8 -> 128 threads, 32 FFMA2 per kk per thread.
// RAW: write unscaled partial to C + blockIdx.z*M*N (split-K), K = per-split K,
//      A/B pre-offset by blockIdx.z*K inside the kernel.
// ---------------------------------------------------------------------------
template<int BM, int BN, int BK, int TM, int TN,
         bool TRANS_A, bool RELU_A, bool GATHER_A,
         bool HAS_BIAS, bool RELU_OUT, bool RAW>
__global__ __launch_bounds__((BM / TM) * (BN / TN))
void gemm_kernel(const float* __restrict__ A, int lda,
                 const float* __restrict__ B,
                 float* __restrict__ C,
                 const float* __restrict__ bias,
                 const float* __restrict__ rowScale,
                 const int*   __restrict__ gatherIdx,
                 int M, int N, int K)
{
    constexpr int NT   = (BM / TM) * (BN / TN);     // 128
    constexpr int APAD = 4;
    constexpr int AV   = (BM * BK) / (4 * NT);      // 4
    constexpr int BV   = (BK * BN) / (4 * NT);      // 2

    __shared__ float As[BK][BM + APAD];
    __shared__ float Bs[BK][BN];

    const int tid = threadIdx.x;
    const int tx  = tid % (BN / TN);
    const int ty  = tid / (BN / TN);
    const int m0  = blockIdx.y * BM;
    const int n0  = blockIdx.x * BN;

    // split-K offsets
    const int kBase = RAW ? blockIdx.z * K : 0;
    const float* Ap = TRANS_A ? (A + (size_t)kBase * lda) : (A + kBase);
    const float* Bp = B + (size_t)kBase * N;
    float* Cp = RAW ? (C + (size_t)blockIdx.z * M * N) : C;

    float4 areg[AV];
    float4 breg[BV];

    unsigned long long acc2[TM][TN / 2];
    #pragma unroll
    for (int i = 0; i < TM; ++i)
        #pragma unroll
        for (int j = 0; j < TN / 2; ++j) acc2[i][j] = 0ull;

    auto loadA = [&](int k0) {
        #pragma unroll
        for (int v = 0; v < AV; ++v) {
            int idx = tid + v * NT;
            float4 t;
            if (TRANS_A) {
                int k  = idx / (BM / 4);
                int m4 = idx % (BM / 4);
                t = *reinterpret_cast<const float4*>(Ap + (size_t)(k0 + k) * lda + (m0 + m4 * 4));
            } else {
                int m  = idx / (BK / 4);
                int kq = idx % (BK / 4);
                int row;
                if (GATHER_A) row = gatherIdx[m0 + m];
                else          row = m0 + m;
                t = *reinterpret_cast<const float4*>(Ap + (size_t)row * lda + (k0 + kq * 4));
            }
            if (RELU_A) {
                t.x = fmaxf(t.x, 0.f); t.y = fmaxf(t.y, 0.f);
                t.z = fmaxf(t.z, 0.f); t.w = fmaxf(t.w, 0.f);
            }
            areg[v] = t;
        }
    };

    auto storeA = [&]() {
        #pragma unroll
        for (int v = 0; v < AV; ++v) {
            int idx = tid + v * NT;
            if (TRANS_A) {
                int k  = idx / (BM / 4);
                int m4 = idx % (BM / 4);
                *reinterpret_cast<float4*>(&As[k][m4 * 4]) = areg[v];
            } else {
                int m  = idx / (BK / 4);
                int kq = idx % (BK / 4);
                As[kq * 4 + 0][m] = areg[v].x;
                As[kq * 4 + 1][m] = areg[v].y;
                As[kq * 4 + 2][m] = areg[v].z;
                As[kq * 4 + 3][m] = areg[v].w;
            }
        }
    };

    auto loadB = [&](int k0) {
        #pragma unroll
        for (int v = 0; v < BV; ++v) {
            int idx = tid + v * NT;
            int k  = idx / (BN / 4);
            int n4 = idx % (BN / 4);
            breg[v] = *reinterpret_cast<const float4*>(Bp + (size_t)(k0 + k) * N + (n0 + n4 * 4));
        }
    };

    auto storeB = [&]() {
        #pragma unroll
        for (int v = 0; v < BV; ++v) {
            int idx = tid + v * NT;
            int k  = idx / (BN / 4);
            int n4 = idx % (BN / 4);
            *reinterpret_cast<float4*>(&Bs[k][n4 * 4]) = breg[v];
        }
    };

    loadA(0); loadB(0);
    storeA(); storeB();
    __syncthreads();

    const int KT = K / BK;
    for (int kt = 0; kt < KT; ++kt) {
        if (kt + 1 < KT) { loadA((kt + 1) * BK); loadB((kt + 1) * BK); }

        #pragma unroll
        for (int kk = 0; kk < BK; ++kk) {
            unsigned long long a2[TM], b2[TN / 2];
            #pragma unroll
            for (int i = 0; i < TM; i += 4) {
                float4 t = *reinterpret_cast<const float4*>(&As[kk][ty * TM + i]);
                asm("mov.b64 %0, {%1, %1};" : "=l"(a2[i + 0]) : "f"(t.x));
                asm("mov.b64 %0, {%1, %1};" : "=l"(a2[i + 1]) : "f"(t.y));
                asm("mov.b64 %0, {%1, %1};" : "=l"(a2[i + 2]) : "f"(t.z));
                asm("mov.b64 %0, {%1, %1};" : "=l"(a2[i + 3]) : "f"(t.w));
            }
            #pragma unroll
            for (int j = 0; j < TN; j += 4) {
                float4 t = *reinterpret_cast<const float4*>(&Bs[kk][tx * TN + j]);
                asm("mov.b64 %0, {%1, %2};" : "=l"(b2[j / 2 + 0]) : "f"(t.x), "f"(t.y));
                asm("mov.b64 %0, {%1, %2};" : "=l"(b2[j / 2 + 1]) : "f"(t.z), "f"(t.w));
            }
            #pragma unroll
            for (int i = 0; i < TM; ++i)
                #pragma unroll
                for (int j = 0; j < TN / 2; ++j)
                    asm("fma.rn.f32x2 %0, %1, %2, %0;"
                        : "+l"(acc2[i][j]) : "l"(a2[i]), "l"(b2[j]));
        }

        if (kt + 1 < KT) {
            __syncthreads();
            storeA(); storeB();
            __syncthreads();
        }
    }

    // epilogue
    #pragma unroll
    for (int i = 0; i < TM; ++i) {
        int row = m0 + ty * TM + i;
        float sc = RAW ? 1.0f : rowScale[row];
        #pragma unroll
        for (int j = 0; j < TN; j += 4) {
            int col = n0 + tx * TN + j;
            float c0, c1, c2, c3;
            asm("mov.b64 {%0, %1}, %2;" : "=f"(c0), "=f"(c1) : "l"(acc2[i][j / 2 + 0]));
            asm("mov.b64 {%0, %1}, %2;" : "=f"(c2), "=f"(c3) : "l"(acc2[i][j / 2 + 1]));
            float4 r;
            if (RAW) {
                r.x = c0; r.y = c1; r.z = c2; r.w = c3;
            } else {
                r.x = c0 * sc; r.y = c1 * sc; r.z = c2 * sc; r.w = c3 * sc;
                if (HAS_BIAS) {
                    float4 bb = *reinterpret_cast<const float4*>(bias + col);
                    r.x += bb.x; r.y += bb.y; r.z += bb.z; r.w += bb.w;
                }
                if (RELU_OUT) {
                    r.x = fmaxf(r.x, 0.f); r.y = fmaxf(r.y, 0.f);
                    r.z = fmaxf(r.z, 0.f); r.w = fmaxf(r.w, 0.f);
                }
            }
            *reinterpret_cast<float4*>(Cp + (size_t)row * N + col) = r;
        }
    }
}

// ---------------------------------------------------------------------------
// Split-K reduction + epilogue for Z:  Z = dis[row] * sum_s part[s] + bias[col]
// ---------------------------------------------------------------------------
__global__ void reduce_z_kernel(const float* __restrict__ bias)
{
    int i4 = blockIdx.x * blockDim.x + threadIdx.x;     // float4 index into [M,N]
    constexpr int MN4 = N_NODES * OUT_C / 4;
    if (i4 >= MN4) return;
    const float4* p = reinterpret_cast<const float4*>(g_part);
    float4 s = p[i4];
    #pragma unroll
    for (int sp = 1; sp < SPLITK_Z; ++sp) {
        float4 v = p[i4 + sp * MN4];
        s.x += v.x; s.y += v.y; s.z += v.z; s.w += v.w;
    }
    int row = (i4 * 4) / OUT_C;
    int col = (i4 * 4) % OUT_C;
    float sc = g_dis[row];
    float4 bb = *reinterpret_cast<const float4*>(bias + col);
    float4 r;
    r.x = s.x * sc + bb.x;
    r.y = s.y * sc + bb.y;
    r.z = s.z * sc + bb.z;
    r.w = s.w * sc + bb.w;
    reinterpret_cast<float4*>(g_Z)[i4] = r;
}

// ---------------------------------------------------------------------------
__global__ void decode_kernel(const int* __restrict__ eli,
                              float* __restrict__ out, int nPred)
{
    int warp = (blockIdx.x * blockDim.x + threadIdx.x) >> 5;
    int lane = threadIdx.x & 31;
    if (warp >= nPred) return;
    int s = eli[warp];
    int d = eli[nPred + warp];
    const float4* zs = reinterpret_cast<const float4*>(g_Z + (size_t)s * OUT_C);
    const float4* zd = reinterpret_cast<const float4*>(g_Z + (size_t)d * OUT_C);
    float4 a = zs[lane];
    float4 b = zd[lane];
    float dot = a.x * b.x + a.y * b.y + a.z * b.z + a.w * b.w;
    #pragma unroll
    for (int o = 16; o; o >>= 1) dot += __shfl_xor_sync(0xffffffffu, dot, o);
    if (lane == 0) out[warp] = dot;
}

// ---------------------------------------------------------------------------
extern "C" void kernel_launch(void* const* d_in, const int* in_sizes, int n_in,
                              void* d_out, int out_size)
{
    const int*   nodeIdx = (const int*)  d_in[0];
    const float* attn    = (const float*)d_in[1];
    const int*   eli     = (const int*)  d_in[2];
    const float* emb     = (const float*)d_in[3];
    const float* W1      = (const float*)d_in[4];
    const float* b1      = (const float*)d_in[5];
    const float* W2      = (const float*)d_in[6];
    const float* b2      = (const float*)d_in[7];
    float* out = (float*)d_out;
    const int nPred = in_sizes[2] / 2;

    float *pDis, *pP, *pH, *pQ, *pPart;
    cudaGetSymbolAddress((void**)&pDis,  g_dis);
    cudaGetSymbolAddress((void**)&pP,    g_P);
    cudaGetSymbolAddress((void**)&pH,    g_H);
    cudaGetSymbolAddress((void**)&pQ,    g_Q);
    cudaGetSymbolAddress((void**)&pPart, g_part);

    // 1) deg / dis
    deg_partial_kernel<<<dim3(N_NODES / (256 * 4), 64), 256>>>(attn);
    dis_kernel<<<N_NODES / 256, 256>>>();

    // 2) P = dis ⊙ (emb[nodeIdx] @ W1)   [8192,256]  NN + gather
    gemm_kernel<128, 64, 16, 8, 8, false, false, true, false, false, false>
        <<<dim3(HID_C / 64, N_NODES / 128), 128>>>(
            emb, E_DIM_C, W1, pP, nullptr, pDis, nodeIdx,
            N_NODES, HID_C, E_DIM_C);

    // 3) H = relu( dis ⊙ (w^T @ P) + b1 )  [8192,256]  TN
    gemm_kernel<128, 64, 16, 8, 8, true, true, false, true, true, false>
        <<<dim3(HID_C / 64, N_NODES / 128), 128>>>(
            attn, N_NODES, pP, pH, b1, pDis, nullptr,
            N_NODES, HID_C, N_NODES);

    // 4) Q = dis ⊙ (H @ W2)   [8192,128]  NN
    gemm_kernel<128, 64, 16, 8, 8, false, false, false, false, false, false>
        <<<dim3(OUT_C / 64, N_NODES / 128), 128>>>(
            pH, HID_C, W2, pQ, nullptr, pDis, nullptr,
            N_NODES, OUT_C, HID_C);

    // 5) Z partials = w^T @ Q  [8192,128]  TN, split-K=2 (raw, no epilogue)
    gemm_kernel<128, 64, 16, 8, 8, true, true, false, false, false, true>
        <<<dim3(OUT_C / 64, N_NODES / 128, SPLITK_Z), 128>>>(
            attn, N_NODES, pQ, pPart, nullptr, nullptr, nullptr,
            N_NODES, OUT_C, N_NODES / SPLITK_Z);

    // 5b) reduce + epilogue -> Z
    {
        int n4 = N_NODES * OUT_C / 4;
        reduce_z_kernel<<<(n4 + 255) / 256, 256>>>(b2);
    }

    // 6) decode
    {
        int warpsPerBlock = 8;
        int blocks = (nPred + warpsPerBlock - 1) / warpsPerBlock;
        decode_kernel<<<blocks, 256>>>(eli, out, nPred);
    }
}

// round 4
// speedup vs baseline: 2.2048x; 1.9951x over previous
#include <cuda_runtime.h>
#include <cuda_bf16.h>
#include <cstdint>

// ---------------------------------------------------------------------------
// GCNEdgePredictorWithEmbeddings — round 3: bf16-split tensor-core attn GEMMs
//   w = relu(attn);  A_norm^T @ Y == dis ⊙ ( w^T @ (dis ⊙ Y) )
//   P = dis ⊙ (emb[node_idx] @ W1)                 (SIMT fp32)
//   Hpart = w^T @ P  (bf16-split TC, split-K=2) ; H = relu(dis⊙ΣHpart + b1)
//   Q = dis ⊙ (H @ W2)                             (SIMT fp32)
//   Zpart = w^T @ Q  (bf16-split TC, split-K=4) ; Z = dis⊙ΣZpart + b2
//   scores[e] = dot(Z[src], Z[dst])
// ---------------------------------------------------------------------------

static constexpr int N_NODES = 8192;
static constexpr int E_DIM_C = 256;
static constexpr int HID_C   = 256;
static constexpr int OUT_C   = 128;

__device__ float g_degp[64 * N_NODES];
__device__ float g_dis [N_NODES];
__device__ float g_P   [N_NODES * HID_C];
__device__ float g_H   [N_NODES * HID_C];
__device__ float g_Q   [N_NODES * OUT_C];
__device__ float g_Z   [N_NODES * OUT_C];
__device__ float g_part[2 * N_NODES * HID_C];   // 2*8192*256 == 4*8192*128 floats

// ---------------------------------------------------------------------------
__global__ void deg_partial_kernel(const float* __restrict__ attn)
{
    int c4 = blockIdx.x * blockDim.x + threadIdx.x;
    int r0 = blockIdx.y * 128;
    float4 s = make_float4(0.f, 0.f, 0.f, 0.f);
    const float4* a = reinterpret_cast<const float4*>(attn);
    #pragma unroll 4
    for (int r = 0; r < 128; ++r) {
        float4 v = a[(size_t)(r0 + r) * (N_NODES / 4) + c4];
        s.x += fmaxf(v.x, 0.f);
        s.y += fmaxf(v.y, 0.f);
        s.z += fmaxf(v.z, 0.f);
        s.w += fmaxf(v.w, 0.f);
    }
    reinterpret_cast<float4*>(g_degp)[blockIdx.y * (N_NODES / 4) + c4] = s;
}

__global__ void dis_kernel()
{
    int col = blockIdx.x * blockDim.x + threadIdx.x;
    float s = 0.f;
    #pragma unroll
    for (int r = 0; r < 64; ++r) s += g_degp[r * N_NODES + col];
    g_dis[col] = (s > 0.f) ? rsqrtf(s) : 0.f;
}

// ---------------------------------------------------------------------------
__device__ __forceinline__ void ldsm_x4_t(uint32_t& r0, uint32_t& r1,
                                          uint32_t& r2, uint32_t& r3, uint32_t addr)
{
    asm volatile("ldmatrix.sync.aligned.m8n8.x4.trans.shared.b16 {%0,%1,%2,%3}, [%4];"
                 : "=r"(r0), "=r"(r1), "=r"(r2), "=r"(r3) : "r"(addr));
}

__device__ __forceinline__ void mma16816(float* d, const uint32_t* a, const uint32_t* b)
{
    asm volatile("mma.sync.aligned.m16n8k16.row.col.f32.bf16.bf16.f32 "
                 "{%0,%1,%2,%3}, {%4,%5,%6,%7}, {%8,%9}, {%0,%1,%2,%3};"
                 : "+f"(d[0]), "+f"(d[1]), "+f"(d[2]), "+f"(d[3])
                 : "r"(a[0]), "r"(a[1]), "r"(a[2]), "r"(a[3]), "r"(b[0]), "r"(b[1]));
}

// Tensor-core GEMM (bf16 split x3):  Cpart[z] = relu(A)^T @ B over K-split z
//   A: [K, M] fp32 row-major (attn), B: [K, N] fp32 row-major.
template<int SPLITK>
__global__ __launch_bounds__(256, 1)
void tc_gemm(const float* __restrict__ A, const float* __restrict__ B,
             float* __restrict__ Cpart, int M, int N, int K)
{
    constexpr int BM = 128, BN = 128, BK = 32;
    constexpr int AP = 136, BP = 136;

    extern __shared__ __nv_bfloat16 smheap[];
    __nv_bfloat16* Ah = smheap;
    __nv_bfloat16* Al = Ah + 2 * BK * AP;
    __nv_bfloat16* Bh = Al + 2 * BK * AP;
    __nv_bfloat16* Bl = Bh + 2 * BK * BP;

    const int tid  = threadIdx.x;
    const int lane = tid & 31;
    const int wid  = tid >> 5;
    const int wm   = (wid >> 2) * 64;
    const int wn   = (wid & 3) * 32;
    const int m0   = blockIdx.y * BM;
    const int n0   = blockIdx.x * BN;
    const int Ksp  = K / SPLITK;
    const int kB   = blockIdx.z * Ksp;
    const int KT   = Ksp / BK;

    float acc[4][4][4];
    #pragma unroll
    for (int i = 0; i < 4; ++i)
        #pragma unroll
        for (int j = 0; j < 4; ++j)
            #pragma unroll
            for (int q = 0; q < 4; ++q) acc[i][j][q] = 0.f;

    float4 aS[4], bS[4];

    auto gload = [&](int kt) {
        int kg = kB + kt * BK;
        #pragma unroll
        for (int v = 0; v < 4; ++v) {
            int idx = tid + v * 256;
            int kr  = idx >> 5;
            int c4  = idx & 31;
            aS[v] = *reinterpret_cast<const float4*>(A + (size_t)(kg + kr) * M + m0 + c4 * 4);
            bS[v] = *reinterpret_cast<const float4*>(B + (size_t)(kg + kr) * N + n0 + c4 * 4);
        }
    };

    auto split2 = [&](__nv_bfloat16* hd, __nv_bfloat16* ld, int off, float x0, float x1) {
        __nv_bfloat16 h0 = __float2bfloat16(x0);
        __nv_bfloat16 h1 = __float2bfloat16(x1);
        __nv_bfloat16 l0 = __float2bfloat16(x0 - __bfloat162float(h0));
        __nv_bfloat16 l1 = __float2bfloat16(x1 - __bfloat162float(h1));
        *reinterpret_cast<__nv_bfloat162*>(hd + off) = __nv_bfloat162(h0, h1);
        *reinterpret_cast<__nv_bfloat162*>(ld + off) = __nv_bfloat162(l0, l1);
    };

    auto sstore = [&](int s) {
        __nv_bfloat16* ah = Ah + s * BK * AP;
        __nv_bfloat16* al = Al + s * BK * AP;
        __nv_bfloat16* bh = Bh + s * BK * BP;
        __nv_bfloat16* bl = Bl + s * BK * BP;
        #pragma unroll
        for (int v = 0; v < 4; ++v) {
            int idx = tid + v * 256;
            int kr  = idx >> 5;
            int c4  = idx & 31;
            float4 a = aS[v];
            a.x = fmaxf(a.x, 0.f); a.y = fmaxf(a.y, 0.f);
            a.z = fmaxf(a.z, 0.f); a.w = fmaxf(a.w, 0.f);
            split2(ah, al, kr * AP + c4 * 4 + 0, a.x, a.y);
            split2(ah, al, kr * AP + c4 * 4 + 2, a.z, a.w);
            float4 b = bS[v];
            split2(bh, bl, kr * BP + c4 * 4 + 0, b.x, b.y);
            split2(bh, bl, kr * BP + c4 * 4 + 2, b.z, b.w);
        }
    };

    const int aRow = (lane & 7) + ((lane >> 4) & 1) * 8;
    const int aCol = wm + ((lane >> 3) & 1) * 8;
    const int bRow = (lane & 7) + ((lane >> 3) & 1) * 8;
    const int bCol = wn + ((lane >> 4) & 1) * 8;

    auto compute = [&](int s) {
        uint32_t ahB = (uint32_t)__cvta_generic_to_shared(Ah + s * BK * AP);
        uint32_t alB = (uint32_t)__cvta_generic_to_shared(Al + s * BK * AP);
        uint32_t bhB = (uint32_t)__cvta_generic_to_shared(Bh + s * BK * BP);
        uint32_t blB = (uint32_t)__cvta_generic_to_shared(Bl + s * BK * BP);
        #pragma unroll
        for (int k16 = 0; k16 < 2; ++k16) {
            int k0 = k16 * 16;
            uint32_t ahf[4][4], alf[4][4];
            #pragma unroll
            for (int mi = 0; mi < 4; ++mi) {
                uint32_t off = ((k0 + aRow) * AP + aCol + mi * 16) * 2;
                ldsm_x4_t(ahf[mi][0], ahf[mi][1], ahf[mi][2], ahf[mi][3], ahB + off);
                ldsm_x4_t(alf[mi][0], alf[mi][1], alf[mi][2], alf[mi][3], alB + off);
            }
            uint32_t bhf[4][2], blf[4][2];
            #pragma unroll
            for (int p = 0; p < 2; ++p) {
                uint32_t off = ((k0 + bRow) * BP + bCol + p * 16) * 2;
                uint32_t r0, r1, r2, r3;
                ldsm_x4_t(r0, r1, r2, r3, bhB + off);
                bhf[2 * p][0] = r0; bhf[2 * p][1] = r1;
                bhf[2 * p + 1][0] = r2; bhf[2 * p + 1][1] = r3;
                ldsm_x4_t(r0, r1, r2, r3, blB + off);
                blf[2 * p][0] = r0; blf[2 * p][1] = r1;
                blf[2 * p + 1][0] = r2; blf[2 * p + 1][1] = r3;
            }
            #pragma unroll
            for (int mi = 0; mi < 4; ++mi)
                #pragma unroll
                for (int ni = 0; ni < 4; ++ni) {
                    mma16816(acc[mi][ni], ahf[mi], bhf[ni]);
                    mma16816(acc[mi][ni], ahf[mi], blf[ni]);
                    mma16816(acc[mi][ni], alf[mi], bhf[ni]);
                }
        }
    };

    gload(0);
    sstore(0);
    __syncthreads();

    int s = 0;
    for (int kt = 0; kt < KT; ++kt) {
        if (kt + 1 < KT) gload(kt + 1);
        compute(s);
        if (kt + 1 < KT) {
            __syncthreads();
            sstore(s ^ 1);
            __syncthreads();
            s ^= 1;
        }
    }

    float* Cp = Cpart + (size_t)blockIdx.z * M * N;
    const int rB = m0 + wm + (lane >> 2);
    const int cB = n0 + wn + (lane & 3) * 2;
    #pragma unroll
    for (int mi = 0; mi < 4; ++mi)
        #pragma unroll
        for (int ni = 0; ni < 4; ++ni) {
            int r = rB + mi * 16;
            int c = cB + ni * 8;
            *reinterpret_cast<float2*>(Cp + (size_t)r * N + c) =
                make_float2(acc[mi][ni][0], acc[mi][ni][1]);
            *reinterpret_cast<float2*>(Cp + (size_t)(r + 8) * N + c) =
                make_float2(acc[mi][ni][2], acc[mi][ni][3]);
        }
}

// ---------------------------------------------------------------------------
template<int SPLITK, bool RELU>
__global__ void reduce_epi_kernel(const float* __restrict__ part,
                                  const float* __restrict__ bias,
                                  float* __restrict__ C, int N)
{
    int i4 = blockIdx.x * blockDim.x + threadIdx.x;
    int MN4 = N_NODES * N / 4;
    if (i4 >= MN4) return;
    const float4* p = reinterpret_cast<const float4*>(part);
    float4 s = p[i4];
    #pragma unroll
    for (int sp = 1; sp < SPLITK; ++sp) {
        float4 v = p[i4 + (size_t)sp * MN4];
        s.x += v.x; s.y += v.y; s.z += v.z; s.w += v.w;
    }
    int row = (i4 * 4) / N;
    int col = (i4 * 4) % N;
    float sc = g_dis[row];
    float4 bb = *reinterpret_cast<const float4*>(bias + col);
    float4 r;
    r.x = s.x * sc + bb.x;
    r.y = s.y * sc + bb.y;
    r.z = s.z * sc + bb.z;
    r.w = s.w * sc + bb.w;
    if (RELU) {
        r.x = fmaxf(r.x, 0.f); r.y = fmaxf(r.y, 0.f);
        r.z = fmaxf(r.z, 0.f); r.w = fmaxf(r.w, 0.f);
    }
    reinterpret_cast<float4*>(C)[i4] = r;
}

// ---------------------------------------------------------------------------
template<int BM, int BN, int BK, int TM, int TN, bool GATHER_A>
__global__ __launch_bounds__((BM / TM) * (BN / TN))
void simt_gemm(const float* __restrict__ A, int lda,
               const float* __restrict__ B,
               float* __restrict__ C,
               const float* __restrict__ rowScale,
               const int* __restrict__ gatherIdx,
               int M, int N, int K)
{
    constexpr int NT   = (BM / TM) * (BN / TN);
    constexpr int APAD = 4;
    constexpr int AV   = (BM * BK) / (4 * NT);
    constexpr int BV   = (BK * BN) / (4 * NT);

    __shared__ float As[BK][BM + APAD];
    __shared__ float Bs[BK][BN];

    const int tid = threadIdx.x;
    const int tx  = tid % (BN / TN);
    const int ty  = tid / (BN / TN);
    const int m0  = blockIdx.y * BM;
    const int n0  = blockIdx.x * BN;

    float4 areg[AV], breg[BV];
    float acc[TM][TN];
    #pragma unroll
    for (int i = 0; i < TM; ++i)
        #pragma unroll
        for (int j = 0; j < TN; ++j) acc[i][j] = 0.f;

    auto loadA = [&](int k0) {
        #pragma unroll
        for (int v = 0; v < AV; ++v) {
            int idx = tid + v * NT;
            int m  = idx / (BK / 4);
            int kq = idx % (BK / 4);
            int row = GATHER_A ? gatherIdx[m0 + m] : (m0 + m);
            areg[v] = *reinterpret_cast<const float4*>(A + (size_t)row * lda + (k0 + kq * 4));
        }
    };
    auto storeA = [&]() {
        #pragma unroll
        for (int v = 0; v < AV; ++v) {
            int idx = tid + v * NT;
            int m  = idx / (BK / 4);
            int kq = idx % (BK / 4);
            As[kq * 4 + 0][m] = areg[v].x;
            As[kq * 4 + 1][m] = areg[v].y;
            As[kq * 4 + 2][m] = areg[v].z;
            As[kq * 4 + 3][m] = areg[v].w;
        }
    };
    auto loadB = [&](int k0) {
        #pragma unroll
        for (int v = 0; v < BV; ++v) {
            int idx = tid + v * NT;
            int k  = idx / (BN / 4);
            int n4 = idx % (BN / 4);
            breg[v] = *reinterpret_cast<const float4*>(B + (size_t)(k0 + k) * N + (n0 + n4 * 4));
        }
    };
    auto storeB = [&]() {
        #pragma unroll
        for (int v = 0; v < BV; ++v) {
            int idx = tid + v * NT;
            int k  = idx / (BN / 4);
            int n4 = idx % (BN / 4);
            *reinterpret_cast<float4*>(&Bs[k][n4 * 4]) = breg[v];
        }
    };

    loadA(0); loadB(0);
    storeA(); storeB();
    __syncthreads();

    const int KT = K / BK;
    for (int kt = 0; kt < KT; ++kt) {
        if (kt + 1 < KT) { loadA((kt + 1) * BK); loadB((kt + 1) * BK); }
        #pragma unroll
        for (int kk = 0; kk < BK; ++kk) {
            float a[TM], b[TN];
            #pragma unroll
            for (int i = 0; i < TM; i += 4) {
                float4 t = *reinterpret_cast<const float4*>(&As[kk][ty * TM + i]);
                a[i] = t.x; a[i + 1] = t.y; a[i + 2] = t.z; a[i + 3] = t.w;
            }
            #pragma unroll
            for (int j = 0; j < TN; j += 4) {
                float4 t = *reinterpret_cast<const float4*>(&Bs[kk][tx * TN + j]);
                b[j] = t.x; b[j + 1] = t.y; b[j + 2] = t.z; b[j + 3] = t.w;
            }
            #pragma unroll
            for (int i = 0; i < TM; ++i)
                #pragma unroll
                for (int j = 0; j < TN; ++j)
                    acc[i][j] = fmaf(a[i], b[j], acc[i][j]);
        }
        if (kt + 1 < KT) {
            __syncthreads();
            storeA(); storeB();
            __syncthreads();
        }
    }

    #pragma unroll
    for (int i = 0; i < TM; ++i) {
        int row = m0 + ty * TM + i;
        float sc = rowScale[row];
        #pragma unroll
        for (int j = 0; j < TN; j += 4) {
            int col = n0 + tx * TN + j;
            float4 r;
            r.x = acc[i][j + 0] * sc;
            r.y = acc[i][j + 1] * sc;
            r.z = acc[i][j + 2] * sc;
            r.w = acc[i][j + 3] * sc;
            *reinterpret_cast<float4*>(C + (size_t)row * N + col) = r;
        }
    }
}

// ---------------------------------------------------------------------------
__global__ void decode_kernel(const int* __restrict__ eli,
                              float* __restrict__ out, int nPred)
{
    int warp = (blockIdx.x * blockDim.x + threadIdx.x) >> 5;
    int lane = threadIdx.x & 31;
    if (warp >= nPred) return;
    int s = eli[warp];
    int d = eli[nPred + warp];
    const float4* zs = reinterpret_cast<const float4*>(g_Z + (size_t)s * OUT_C);
    const float4* zd = reinterpret_cast<const float4*>(g_Z + (size_t)d * OUT_C);
    float4 a = zs[lane];
    float4 b = zd[lane];
    float dot = a.x * b.x + a.y * b.y + a.z * b.z + a.w * b.w;
    #pragma unroll
    for (int o = 16; o; o >>= 1) dot += __shfl_xor_sync(0xffffffffu, dot, o);
    if (lane == 0) out[warp] = dot;
}

// ---------------------------------------------------------------------------
extern "C" void kernel_launch(void* const* d_in, const int* in_sizes, int n_in,
                              void* d_out, int out_size)
{
    const int*   nodeIdx = (const int*)  d_in[0];
    const float* attn    = (const float*)d_in[1];
    const int*   eli     = (const int*)  d_in[2];
    const float* emb     = (const float*)d_in[3];
    const float* W1      = (const float*)d_in[4];
    const float* b1      = (const float*)d_in[5];
    const float* W2      = (const float*)d_in[6];
    const float* b2      = (const float*)d_in[7];
    float* out = (float*)d_out;
    const int nPred = in_sizes[2] / 2;

    float *pDis, *pP, *pH, *pQ, *pZ, *pPart;
    cudaGetSymbolAddress((void**)&pDis,  g_dis);
    cudaGetSymbolAddress((void**)&pP,    g_P);
    cudaGetSymbolAddress((void**)&pH,    g_H);
    cudaGetSymbolAddress((void**)&pQ,    g_Q);
    cudaGetSymbolAddress((void**)&pZ,    g_Z);
    cudaGetSymbolAddress((void**)&pPart, g_part);

    constexpr int TC_SMEM = (4 * 2 * 32 * 136) * 2;   // 69632 bytes
    cudaFuncSetAttribute(tc_gemm<2>, cudaFuncAttributeMaxDynamicSharedMemorySize, TC_SMEM);
    cudaFuncSetAttribute(tc_gemm<4>, cudaFuncAttributeMaxDynamicSharedMemorySize, TC_SMEM);

    // 1) deg / dis
    deg_partial_kernel<<<dim3(N_NODES / (256 * 4), 64), 256>>>(attn);
    dis_kernel<<<N_NODES / 256, 256>>>();

    // 2) P = dis ⊙ (emb[nodeIdx] @ W1)   [8192,256]
    simt_gemm<128, 64, 16, 8, 8, true>
        <<<dim3(HID_C / 64, N_NODES / 128), 128>>>(
            emb, E_DIM_C, W1, pP, pDis, nodeIdx, N_NODES, HID_C, E_DIM_C);

    // 3) H partials = relu(attn)^T @ P  [8192,256], split-K=2 (TC)
    tc_gemm<2><<<dim3(HID_C / 128, N_NODES / 128, 2), 256, TC_SMEM>>>(
        attn, pP, pPart, N_NODES, HID_C, N_NODES);
    reduce_epi_kernel<2, true>
        <<<(N_NODES * HID_C / 4 + 255) / 256, 256>>>(pPart, b1, pH, HID_C);

    // 4) Q = dis ⊙ (H @ W2)   [8192,128]
    simt_gemm<128, 64, 16, 8, 8, false>
        <<<dim3(OUT_C / 64, N_NODES / 128), 128>>>(
            pH, HID_C, W2, pQ, pDis, nullptr, N_NODES, OUT_C, HID_C);

    // 5) Z partials = relu(attn)^T @ Q  [8192,128], split-K=4 (TC)
    tc_gemm<4><<<dim3(OUT_C / 128, N_NODES / 128, 4), 256, TC_SMEM>>>(
        attn, pQ, pPart, N_NODES, OUT_C, N_NODES);
    reduce_epi_kernel<4, false>
        <<<(N_NODES * OUT_C / 4 + 255) / 256, 256>>>(pPart, b2, pZ, OUT_C);

    // 6) decode
    {
        int blocks = (nPred + 7) / 8;
        decode_kernel<<<blocks, 256>>>(eli, out, nPred);
    }
}

// round 5
// speedup vs baseline: 2.2559x; 1.0232x over previous
#include <cuda_runtime.h>
#include <cuda_bf16.h>
#include <cstdint>

// ---------------------------------------------------------------------------
// Round 4: pre-converted bf16-split attn + cp.async tensor-core GEMMs
//   w = relu(attn);  A_norm^T @ Y == dis ⊙ ( w^T @ (dis ⊙ Y) )
//   convert pass: Ah/Al = bf16 split of relu(attn), + deg partials (fused)
//   P  = dis ⊙ (emb[node_idx] @ W1)        (SIMT fp32 -> bf16 hi/lo)
//   H  = relu(dis ⊙ Σ(w^T @ P) + b1)       (TC split-K=2 + reduce)
//   Q  = dis ⊙ (H @ W2)                    (SIMT fp32 -> bf16 hi/lo)
//   Z  = dis ⊙ Σ(w^T @ Q) + b2            (TC split-K=4 + reduce)
//   scores[e] = dot(Z[src], Z[dst])
// ---------------------------------------------------------------------------

static constexpr int N_NODES = 8192;
static constexpr int E_DIM_C = 256;
static constexpr int HID_C   = 256;
static constexpr int OUT_C   = 128;

__device__ float          g_degp[64 * N_NODES];
__device__ float          g_dis [N_NODES];
__device__ __nv_bfloat16  g_Ah  [(size_t)N_NODES * N_NODES];   // 128 MB
__device__ __nv_bfloat16  g_Al  [(size_t)N_NODES * N_NODES];   // 128 MB
__device__ __nv_bfloat16  g_Bh  [N_NODES * HID_C];             // P/Q hi
__device__ __nv_bfloat16  g_Bl  [N_NODES * HID_C];             // P/Q lo
__device__ float          g_H   [N_NODES * HID_C];
__device__ float          g_Z   [N_NODES * OUT_C];
__device__ float          g_part[2 * N_NODES * HID_C];         // split-K partials

// ---------------------------------------------------------------------------
__device__ __forceinline__ uint32_t packbf2(float a, float b)
{
    __nv_bfloat162 t(__float2bfloat16(a), __float2bfloat16(b));
    return *reinterpret_cast<uint32_t*>(&t);
}
__device__ __forceinline__ float bf16of(float x)
{
    return __bfloat162float(__float2bfloat16(x));
}

// ---------------------------------------------------------------------------
// Fused convert + deg: read attn once; write relu'd hi/lo bf16; col partials.
// grid (8, 64), 256 threads; thread handles 4 cols x 128 rows.
// ---------------------------------------------------------------------------
__global__ void convert_deg_kernel(const float* __restrict__ attn)
{
    int c4 = blockIdx.x * blockDim.x + threadIdx.x;   // float4 col index
    int r0 = blockIdx.y * 128;
    float4 s = make_float4(0.f, 0.f, 0.f, 0.f);
    const float4* a = reinterpret_cast<const float4*>(attn);
    #pragma unroll 4
    for (int r = 0; r < 128; ++r) {
        size_t row = r0 + r;
        float4 v = a[row * (N_NODES / 4) + c4];
        v.x = fmaxf(v.x, 0.f); v.y = fmaxf(v.y, 0.f);
        v.z = fmaxf(v.z, 0.f); v.w = fmaxf(v.w, 0.f);
        s.x += v.x; s.y += v.y; s.z += v.z; s.w += v.w;
        uint2 h, l;
        h.x = packbf2(v.x, v.y);
        h.y = packbf2(v.z, v.w);
        l.x = packbf2(v.x - bf16of(v.x), v.y - bf16of(v.y));
        l.y = packbf2(v.z - bf16of(v.z), v.w - bf16of(v.w));
        size_t off = (row * N_NODES) / 4 + c4;        // uint2 index
        reinterpret_cast<uint2*>(g_Ah)[off] = h;
        reinterpret_cast<uint2*>(g_Al)[off] = l;
    }
    reinterpret_cast<float4*>(g_degp)[blockIdx.y * (N_NODES / 4) + c4] = s;
}

__global__ void dis_kernel()
{
    int col = blockIdx.x * blockDim.x + threadIdx.x;
    float s = 0.f;
    #pragma unroll
    for (int r = 0; r < 64; ++r) s += g_degp[r * N_NODES + col];
    g_dis[col] = (s > 0.f) ? rsqrtf(s) : 0.f;
}

// ---------------------------------------------------------------------------
__device__ __forceinline__ void ldsm_x4_t(uint32_t& r0, uint32_t& r1,
                                          uint32_t& r2, uint32_t& r3, uint32_t addr)
{
    asm volatile("ldmatrix.sync.aligned.m8n8.x4.trans.shared.b16 {%0,%1,%2,%3}, [%4];"
                 : "=r"(r0), "=r"(r1), "=r"(r2), "=r"(r3) : "r"(addr));
}

__device__ __forceinline__ void mma16816(float* d, const uint32_t* a, const uint32_t* b)
{
    asm volatile("mma.sync.aligned.m16n8k16.row.col.f32.bf16.bf16.f32 "
                 "{%0,%1,%2,%3}, {%4,%5,%6,%7}, {%8,%9}, {%0,%1,%2,%3};"
                 : "+f"(d[0]), "+f"(d[1]), "+f"(d[2]), "+f"(d[3])
                 : "r"(a[0]), "r"(a[1]), "r"(a[2]), "r"(a[3]), "r"(b[0]), "r"(b[1]));
}

__device__ __forceinline__ void cpasync16(uint32_t smem, const void* gmem)
{
    asm volatile("cp.async.cg.shared.global [%0], [%1], 16;" :: "r"(smem), "l"(gmem));
}

// ---------------------------------------------------------------------------
// TC GEMM on pre-converted bf16:  Cpart[z] = Ahi/lo^T(ish) @ Bhi/lo (3-MMA split)
//   Ah/Al: [K, M] bf16 row-major, Bh/Bl: [K, N] bf16 row-major.
// BM=128, BN=128, BK=32, 256 threads, warp tile 64x32; cp.async 2-stage.
// ---------------------------------------------------------------------------
template<int SPLITK>
__global__ __launch_bounds__(256, 1)
void tc_gemm(const __nv_bfloat16* __restrict__ Ahg,
             const __nv_bfloat16* __restrict__ Alg,
             const __nv_bfloat16* __restrict__ Bhg,
             const __nv_bfloat16* __restrict__ Blg,
             float* __restrict__ Cpart, int M, int N, int K)
{
    constexpr int BM = 128, BN = 128, BK = 32;
    constexpr int AP = 136;                            // bf16 pitch (272 B)
    constexpr int STG = BK * AP;                       // elems per plane per stage

    extern __shared__ __nv_bfloat16 smheap[];
    // layout: [stage][plane(Ah,Al,Bh,Bl)][BK*AP]
    auto plane = [&](int s, int p) { return smheap + (s * 4 + p) * STG; };

    const int tid  = threadIdx.x;
    const int lane = tid & 31;
    const int wid  = tid >> 5;
    const int wm   = (wid >> 2) * 64;
    const int wn   = (wid & 3) * 32;
    const int m0   = blockIdx.y * BM;
    const int n0   = blockIdx.x * BN;
    const int Ksp  = K / SPLITK;
    const int kB   = blockIdx.z * Ksp;
    const int KT   = Ksp / BK;

    float acc[4][4][4];
    #pragma unroll
    for (int i = 0; i < 4; ++i)
        #pragma unroll
        for (int j = 0; j < 4; ++j)
            #pragma unroll
            for (int q = 0; q < 4; ++q) acc[i][j][q] = 0.f;

    // cp.async issue for one stage: each plane 32 rows x 128 bf16 = 512 x 16B
    auto issue = [&](int kt, int s) {
        int kg = kB + kt * BK;
        uint32_t base = (uint32_t)__cvta_generic_to_shared(plane(s, 0));
        #pragma unroll
        for (int v = 0; v < 2; ++v) {
            int idx  = tid + v * 256;
            int row  = idx >> 4;            // 0..31
            int c16  = idx & 15;            // 16B chunk in row
            uint32_t so = row * (AP * 2) + c16 * 16;
            size_t   aoff = (size_t)(kg + row) * M + m0 + c16 * 8;
            size_t   boff = (size_t)(kg + row) * N + n0 + c16 * 8;
            cpasync16(base + 0 * STG * 2 + so, Ahg + aoff);
            cpasync16(base + 1 * STG * 2 + so, Alg + aoff);
            cpasync16(base + 2 * STG * 2 + so, Bhg + boff);
            cpasync16(base + 3 * STG * 2 + so, Blg + boff);
        }
        asm volatile("cp.async.commit_group;");
    };

    const int aRow = (lane & 7) + ((lane >> 4) & 1) * 8;
    const int aCol = wm + ((lane >> 3) & 1) * 8;
    const int bRow = (lane & 7) + ((lane >> 3) & 1) * 8;
    const int bCol = wn + ((lane >> 4) & 1) * 8;

    auto compute = [&](int s) {
        uint32_t ahB = (uint32_t)__cvta_generic_to_shared(plane(s, 0));
        uint32_t alB = (uint32_t)__cvta_generic_to_shared(plane(s, 1));
        uint32_t bhB = (uint32_t)__cvta_generic_to_shared(plane(s, 2));
        uint32_t blB = (uint32_t)__cvta_generic_to_shared(plane(s, 3));
        #pragma unroll
        for (int k16 = 0; k16 < 2; ++k16) {
            int k0 = k16 * 16;
            uint32_t ahf[4][4], alf[4][4];
            #pragma unroll
            for (int mi = 0; mi < 4; ++mi) {
                uint32_t off = ((k0 + aRow) * AP + aCol + mi * 16) * 2;
                ldsm_x4_t(ahf[mi][0], ahf[mi][1], ahf[mi][2], ahf[mi][3], ahB + off);
                ldsm_x4_t(alf[mi][0], alf[mi][1], alf[mi][2], alf[mi][3], alB + off);
            }
            uint32_t bhf[4][2], blf[4][2];
            #pragma unroll
            for (int p = 0; p < 2; ++p) {
                uint32_t off = ((k0 + bRow) * AP + bCol + p * 16) * 2;
                uint32_t r0, r1, r2, r3;
                ldsm_x4_t(r0, r1, r2, r3, bhB + off);
                bhf[2 * p][0] = r0; bhf[2 * p][1] = r1;
                bhf[2 * p + 1][0] = r2; bhf[2 * p + 1][1] = r3;
                ldsm_x4_t(r0, r1, r2, r3, blB + off);
                blf[2 * p][0] = r0; blf[2 * p][1] = r1;
                blf[2 * p + 1][0] = r2; blf[2 * p + 1][1] = r3;
            }
            #pragma unroll
            for (int mi = 0; mi < 4; ++mi)
                #pragma unroll
                for (int ni = 0; ni < 4; ++ni) {
                    mma16816(acc[mi][ni], ahf[mi], bhf[ni]);
                    mma16816(acc[mi][ni], ahf[mi], blf[ni]);
                    mma16816(acc[mi][ni], alf[mi], bhf[ni]);
                }
        }
    };

    issue(0, 0);
    for (int kt = 0; kt < KT; ++kt) {
        if (kt + 1 < KT) {
            issue(kt + 1, (kt + 1) & 1);
            asm volatile("cp.async.wait_group 1;");
        } else {
            asm volatile("cp.async.wait_group 0;");
        }
        __syncthreads();
        compute(kt & 1);
        __syncthreads();
    }

    float* Cp = Cpart + (size_t)blockIdx.z * M * N;
    const int rB = m0 + wm + (lane >> 2);
    const int cB = n0 + wn + (lane & 3) * 2;
    #pragma unroll
    for (int mi = 0; mi < 4; ++mi)
        #pragma unroll
        for (int ni = 0; ni < 4; ++ni) {
            int r = rB + mi * 16;
            int c = cB + ni * 8;
            *reinterpret_cast<float2*>(Cp + (size_t)r * N + c) =
                make_float2(acc[mi][ni][0], acc[mi][ni][1]);
            *reinterpret_cast<float2*>(Cp + (size_t)(r + 8) * N + c) =
                make_float2(acc[mi][ni][2], acc[mi][ni][3]);
        }
}

// ---------------------------------------------------------------------------
template<int SPLITK, bool RELU>
__global__ void reduce_epi_kernel(const float* __restrict__ part,
                                  const float* __restrict__ bias,
                                  float* __restrict__ C, int N)
{
    int i4 = blockIdx.x * blockDim.x + threadIdx.x;
    int MN4 = N_NODES * N / 4;
    if (i4 >= MN4) return;
    const float4* p = reinterpret_cast<const float4*>(part);
    float4 s = p[i4];
    #pragma unroll
    for (int sp = 1; sp < SPLITK; ++sp) {
        float4 v = p[i4 + (size_t)sp * MN4];
        s.x += v.x; s.y += v.y; s.z += v.z; s.w += v.w;
    }
    int row = (i4 * 4) / N;
    int col = (i4 * 4) % N;
    float sc = g_dis[row];
    float4 bb = *reinterpret_cast<const float4*>(bias + col);
    float4 r;
    r.x = s.x * sc + bb.x;
    r.y = s.y * sc + bb.y;
    r.z = s.z * sc + bb.z;
    r.w = s.w * sc + bb.w;
    if (RELU) {
        r.x = fmaxf(r.x, 0.f); r.y = fmaxf(r.y, 0.f);
        r.z = fmaxf(r.z, 0.f); r.w = fmaxf(r.w, 0.f);
    }
    reinterpret_cast<float4*>(C)[i4] = r;
}

// ---------------------------------------------------------------------------
// SIMT fp32 GEMM; epilogue writes bf16 hi/lo planes (B operands for TC GEMMs).
// ---------------------------------------------------------------------------
template<int BM, int BN, int BK, int TM, int TN, bool GATHER_A>
__global__ __launch_bounds__((BM / TM) * (BN / TN))
void simt_gemm(const float* __restrict__ A, int lda,
               const float* __restrict__ B,
               __nv_bfloat16* __restrict__ Ch,
               __nv_bfloat16* __restrict__ Cl,
               const float* __restrict__ rowScale,
               const int* __restrict__ gatherIdx,
               int M, int N, int K)
{
    constexpr int NT   = (BM / TM) * (BN / TN);
    constexpr int APAD = 4;
    constexpr int AV   = (BM * BK) / (4 * NT);
    constexpr int BV   = (BK * BN) / (4 * NT);

    __shared__ float As[BK][BM + APAD];
    __shared__ float Bs[BK][BN];

    const int tid = threadIdx.x;
    const int tx  = tid % (BN / TN);
    const int ty  = tid / (BN / TN);
    const int m0  = blockIdx.y * BM;
    const int n0  = blockIdx.x * BN;

    float4 areg[AV], breg[BV];
    float acc[TM][TN];
    #pragma unroll
    for (int i = 0; i < TM; ++i)
        #pragma unroll
        for (int j = 0; j < TN; ++j) acc[i][j] = 0.f;

    auto loadA = [&](int k0) {
        #pragma unroll
        for (int v = 0; v < AV; ++v) {
            int idx = tid + v * NT;
            int m  = idx / (BK / 4);
            int kq = idx % (BK / 4);
            int row = GATHER_A ? gatherIdx[m0 + m] : (m0 + m);
            areg[v] = *reinterpret_cast<const float4*>(A + (size_t)row * lda + (k0 + kq * 4));
        }
    };
    auto storeA = [&]() {
        #pragma unroll
        for (int v = 0; v < AV; ++v) {
            int idx = tid + v * NT;
            int m  = idx / (BK / 4);
            int kq = idx % (BK / 4);
            As[kq * 4 + 0][m] = areg[v].x;
            As[kq * 4 + 1][m] = areg[v].y;
            As[kq * 4 + 2][m] = areg[v].z;
            As[kq * 4 + 3][m] = areg[v].w;
        }
    };
    auto loadB = [&](int k0) {
        #pragma unroll
        for (int v = 0; v < BV; ++v) {
            int idx = tid + v * NT;
            int k  = idx / (BN / 4);
            int n4 = idx % (BN / 4);
            breg[v] = *reinterpret_cast<const float4*>(B + (size_t)(k0 + k) * N + (n0 + n4 * 4));
        }
    };
    auto storeB = [&]() {
        #pragma unroll
        for (int v = 0; v < BV; ++v) {
            int idx = tid + v * NT;
            int k  = idx / (BN / 4);
            int n4 = idx % (BN / 4);
            *reinterpret_cast<float4*>(&Bs[k][n4 * 4]) = breg[v];
        }
    };

    loadA(0); loadB(0);
    storeA(); storeB();
    __syncthreads();

    const int KT = K / BK;
    for (int kt = 0; kt < KT; ++kt) {
        if (kt + 1 < KT) { loadA((kt + 1) * BK); loadB((kt + 1) * BK); }
        #pragma unroll
        for (int kk = 0; kk < BK; ++kk) {
            float a[TM], b[TN];
            #pragma unroll
            for (int i = 0; i < TM; i += 4) {
                float4 t = *reinterpret_cast<const float4*>(&As[kk][ty * TM + i]);
                a[i] = t.x; a[i + 1] = t.y; a[i + 2] = t.z; a[i + 3] = t.w;
            }
            #pragma unroll
            for (int j = 0; j < TN; j += 4) {
                float4 t = *reinterpret_cast<const float4*>(&Bs[kk][tx * TN + j]);
                b[j] = t.x; b[j + 1] = t.y; b[j + 2] = t.z; b[j + 3] = t.w;
            }
            #pragma unroll
            for (int i = 0; i < TM; ++i)
                #pragma unroll
                for (int j = 0; j < TN; ++j)
                    acc[i][j] = fmaf(a[i], b[j], acc[i][j]);
        }
        if (kt + 1 < KT) {
            __syncthreads();
            storeA(); storeB();
            __syncthreads();
        }
    }

    #pragma unroll
    for (int i = 0; i < TM; ++i) {
        int row = m0 + ty * TM + i;
        float sc = rowScale[row];
        #pragma unroll
        for (int j = 0; j < TN; j += 4) {
            int col = n0 + tx * TN + j;
            float x0 = acc[i][j + 0] * sc;
            float x1 = acc[i][j + 1] * sc;
            float x2 = acc[i][j + 2] * sc;
            float x3 = acc[i][j + 3] * sc;
            uint2 h, l;
            h.x = packbf2(x0, x1);
            h.y = packbf2(x2, x3);
            l.x = packbf2(x0 - bf16of(x0), x1 - bf16of(x1));
            l.y = packbf2(x2 - bf16of(x2), x3 - bf16of(x3));
            size_t off = ((size_t)row * N + col) / 4;
            reinterpret_cast<uint2*>(Ch)[off] = h;
            reinterpret_cast<uint2*>(Cl)[off] = l;
        }
    }
}

// ---------------------------------------------------------------------------
__global__ void decode_kernel(const int* __restrict__ eli,
                              float* __restrict__ out, int nPred)
{
    int warp = (blockIdx.x * blockDim.x + threadIdx.x) >> 5;
    int lane = threadIdx.x & 31;
    if (warp >= nPred) return;
    int s = eli[warp];
    int d = eli[nPred + warp];
    const float4* zs = reinterpret_cast<const float4*>(g_Z + (size_t)s * OUT_C);
    const float4* zd = reinterpret_cast<const float4*>(g_Z + (size_t)d * OUT_C);
    float4 a = zs[lane];
    float4 b = zd[lane];
    float dot = a.x * b.x + a.y * b.y + a.z * b.z + a.w * b.w;
    #pragma unroll
    for (int o = 16; o; o >>= 1) dot += __shfl_xor_sync(0xffffffffu, dot, o);
    if (lane == 0) out[warp] = dot;
}

// ---------------------------------------------------------------------------
extern "C" void kernel_launch(void* const* d_in, const int* in_sizes, int n_in,
                              void* d_out, int out_size)
{
    const int*   nodeIdx = (const int*)  d_in[0];
    const float* attn    = (const float*)d_in[1];
    const int*   eli     = (const int*)  d_in[2];
    const float* emb     = (const float*)d_in[3];
    const float* W1      = (const float*)d_in[4];
    const float* b1      = (const float*)d_in[5];
    const float* W2      = (const float*)d_in[6];
    const float* b2      = (const float*)d_in[7];
    float* out = (float*)d_out;
    const int nPred = in_sizes[2] / 2;

    float *pDis, *pH, *pZ, *pPart;
    __nv_bfloat16 *pAh, *pAl, *pBh, *pBl;
    cudaGetSymbolAddress((void**)&pDis,  g_dis);
    cudaGetSymbolAddress((void**)&pH,    g_H);
    cudaGetSymbolAddress((void**)&pZ,    g_Z);
    cudaGetSymbolAddress((void**)&pPart, g_part);
    cudaGetSymbolAddress((void**)&pAh,   g_Ah);
    cudaGetSymbolAddress((void**)&pAl,   g_Al);
    cudaGetSymbolAddress((void**)&pBh,   g_Bh);
    cudaGetSymbolAddress((void**)&pBl,   g_Bl);

    constexpr int TC_SMEM = 2 * 4 * 32 * 136 * 2;   // 2 stages x 4 planes = 69632 B
    cudaFuncSetAttribute(tc_gemm<2>, cudaFuncAttributeMaxDynamicSharedMemorySize, TC_SMEM);
    cudaFuncSetAttribute(tc_gemm<4>, cudaFuncAttributeMaxDynamicSharedMemorySize, TC_SMEM);

    // 1) convert + deg (fused), then dis
    convert_deg_kernel<<<dim3(8, 64), 256>>>(attn);
    dis_kernel<<<N_NODES / 256, 256>>>();

    // 2) P (bf16 hi/lo) = dis ⊙ (emb[nodeIdx] @ W1)
    simt_gemm<128, 64, 16, 8, 8, true>
        <<<dim3(HID_C / 64, N_NODES / 128), 128>>>(
            emb, E_DIM_C, W1, pBh, pBl, pDis, nodeIdx, N_NODES, HID_C, E_DIM_C);

    // 3) H partials = w^T @ P   split-K=2 (TC, cp.async)
    tc_gemm<2><<<dim3(HID_C / 128, N_NODES / 128, 2), 256, TC_SMEM>>>(
        pAh, pAl, pBh, pBl, pPart, N_NODES, HID_C, N_NODES);
    reduce_epi_kernel<2, true>
        <<<(N_NODES * HID_C / 4 + 255) / 256, 256>>>(pPart, b1, pH, HID_C);

    // 4) Q (bf16 hi/lo) = dis ⊙ (H @ W2)
    simt_gemm<128, 64, 16, 8, 8, false>
        <<<dim3(OUT_C / 64, N_NODES / 128), 128>>>(
            pH, HID_C, W2, pBh, pBl, pDis, nullptr, N_NODES, OUT_C, HID_C);

    // 5) Z partials = w^T @ Q   split-K=4 (TC, cp.async)
    tc_gemm<4><<<dim3(OUT_C / 128, N_NODES / 128, 4), 256, TC_SMEM>>>(
        pAh, pAl, pBh, pBl, pPart, N_NODES, OUT_C, N_NODES);
    reduce_epi_kernel<4, false>
        <<<(N_NODES * OUT_C / 4 + 255) / 256, 256>>>(pPart, b2, pZ, OUT_C);

    // 6) decode
    decode_kernel<<<(nPred + 7) / 8, 256>>>(eli, out, nPred);
}

// round 7
// speedup vs baseline: 2.4640x; 1.0923x over previous
#include <cuda_runtime.h>
#include <cuda_bf16.h>
#include <cstdint>

// ---------------------------------------------------------------------------
// Round 6: mma.sync pipeline (R4) + 2 CTA/SM TC kernels + sorted decode.
//   w = relu(attn);  A_norm^T @ Y == dis ⊙ ( w^T @ (dis ⊙ Y) )
//   convert pass: Ah/Al = bf16 split of relu(attn), + deg partials (fused)
//   P  = dis ⊙ (emb[node_idx] @ W1)        (SIMT fp32 -> bf16 hi/lo)
//   H  = relu(dis ⊙ Σ(w^T @ P) + b1)       (TC split-K=2 + reduce)
//   Q  = dis ⊙ (H @ W2)                    (SIMT fp32 -> bf16 hi/lo)
//   Z  = dis ⊙ Σ(w^T @ Q) + b2            (TC split-K=4 + reduce)
//   decode: bucket-sort edges by src, cache z[src] in smem, dot with z[dst]
// ---------------------------------------------------------------------------

static constexpr int N_NODES = 8192;
static constexpr int E_DIM_C = 256;
static constexpr int HID_C   = 256;
static constexpr int OUT_C   = 128;
static constexpr int MAX_PRED = 2100000;

__device__ float          g_degp[64 * N_NODES];
__device__ float          g_dis [N_NODES];
__device__ __nv_bfloat16  g_Ah  [(size_t)N_NODES * N_NODES];   // 128 MB
__device__ __nv_bfloat16  g_Al  [(size_t)N_NODES * N_NODES];   // 128 MB
__device__ __nv_bfloat16  g_Bh  [N_NODES * HID_C];
__device__ __nv_bfloat16  g_Bl  [N_NODES * HID_C];
__device__ float          g_H   [N_NODES * HID_C];
__device__ float          g_Z   [N_NODES * OUT_C];
__device__ float          g_part[2 * N_NODES * HID_C];
// decode sort scratch
__device__ int            g_cnt  [N_NODES];
__device__ int            g_start[N_NODES + 1];
__device__ int            g_cur  [N_NODES];
__device__ int            g_sdst [MAX_PRED];
__device__ int            g_seid [MAX_PRED];

// ---------------------------------------------------------------------------
__device__ __forceinline__ uint32_t packbf2(float a, float b)
{
    __nv_bfloat162 t(__float2bfloat16(a), __float2bfloat16(b));
    return *reinterpret_cast<uint32_t*>(&t);
}
__device__ __forceinline__ float bf16of(float x)
{
    return __bfloat162float(__float2bfloat16(x));
}

// ---------------------------------------------------------------------------
// Fused convert + deg: read attn once; write relu'd hi/lo bf16; col partials.
// ---------------------------------------------------------------------------
__global__ void convert_deg_kernel(const float* __restrict__ attn)
{
    int c4 = blockIdx.x * blockDim.x + threadIdx.x;
    int r0 = blockIdx.y * 128;
    float4 s = make_float4(0.f, 0.f, 0.f, 0.f);
    const float4* a = reinterpret_cast<const float4*>(attn);
    #pragma unroll 4
    for (int r = 0; r < 128; ++r) {
        size_t row = r0 + r;
        float4 v = a[row * (N_NODES / 4) + c4];
        v.x = fmaxf(v.x, 0.f); v.y = fmaxf(v.y, 0.f);
        v.z = fmaxf(v.z, 0.f); v.w = fmaxf(v.w, 0.f);
        s.x += v.x; s.y += v.y; s.z += v.z; s.w += v.w;
        uint2 h, l;
        h.x = packbf2(v.x, v.y);
        h.y = packbf2(v.z, v.w);
        l.x = packbf2(v.x - bf16of(v.x), v.y - bf16of(v.y));
        l.y = packbf2(v.z - bf16of(v.z), v.w - bf16of(v.w));
        size_t off = (row * N_NODES) / 4 + c4;
        reinterpret_cast<uint2*>(g_Ah)[off] = h;
        reinterpret_cast<uint2*>(g_Al)[off] = l;
    }
    reinterpret_cast<float4*>(g_degp)[blockIdx.y * (N_NODES / 4) + c4] = s;
}

__global__ void dis_kernel()
{
    int col = blockIdx.x * blockDim.x + threadIdx.x;
    float s = 0.f;
    #pragma unroll
    for (int r = 0; r < 64; ++r) s += g_degp[r * N_NODES + col];
    g_dis[col] = (s > 0.f) ? rsqrtf(s) : 0.f;
}

// ---------------------------------------------------------------------------
__device__ __forceinline__ void ldsm_x4_t(uint32_t& r0, uint32_t& r1,
                                          uint32_t& r2, uint32_t& r3, uint32_t addr)
{
    asm volatile("ldmatrix.sync.aligned.m8n8.x4.trans.shared.b16 {%0,%1,%2,%3}, [%4];"
                 : "=r"(r0), "=r"(r1), "=r"(r2), "=r"(r3) : "r"(addr));
}

__device__ __forceinline__ void mma16816(float* d, const uint32_t* a, const uint32_t* b)
{
    asm volatile("mma.sync.aligned.m16n8k16.row.col.f32.bf16.bf16.f32 "
                 "{%0,%1,%2,%3}, {%4,%5,%6,%7}, {%8,%9}, {%0,%1,%2,%3};"
                 : "+f"(d[0]), "+f"(d[1]), "+f"(d[2]), "+f"(d[3])
                 : "r"(a[0]), "r"(a[1]), "r"(a[2]), "r"(a[3]), "r"(b[0]), "r"(b[1]));
}

__device__ __forceinline__ void cpasync16(uint32_t smem, const void* gmem)
{
    asm volatile("cp.async.cg.shared.global [%0], [%1], 16;" :: "r"(smem), "l"(gmem));
}

// ---------------------------------------------------------------------------
// TC GEMM on pre-converted bf16 (3-MMA hi/lo split), 2 CTAs/SM.
//   Ah/Al: [K, M] bf16 row-major, Bh/Bl: [K, N] bf16 row-major.
// BM=128, BN=128, BK=32, 256 threads, warp tile 64x32; cp.async 2-stage.
// ---------------------------------------------------------------------------
template<int SPLITK>
__global__ __launch_bounds__(256, 2)
void tc_gemm(const __nv_bfloat16* __restrict__ Ahg,
             const __nv_bfloat16* __restrict__ Alg,
             const __nv_bfloat16* __restrict__ Bhg,
             const __nv_bfloat16* __restrict__ Blg,
             float* __restrict__ Cpart, int M, int N, int K)
{
    constexpr int BM = 128, BN = 128, BK = 32;
    constexpr int AP = 136;
    constexpr int STG = BK * AP;

    extern __shared__ __nv_bfloat16 smheap[];
    auto plane = [&](int s, int p) { return smheap + (s * 4 + p) * STG; };

    const int tid  = threadIdx.x;
    const int lane = tid & 31;
    const int wid  = tid >> 5;
    const int wm   = (wid >> 2) * 64;
    const int wn   = (wid & 3) * 32;
    const int m0   = blockIdx.y * BM;
    const int n0   = blockIdx.x * BN;
    const int Ksp  = K / SPLITK;
    const int kB   = blockIdx.z * Ksp;
    const int KT   = Ksp / BK;

    float acc[4][4][4];
    #pragma unroll
    for (int i = 0; i < 4; ++i)
        #pragma unroll
        for (int j = 0; j < 4; ++j)
            #pragma unroll
            for (int q = 0; q < 4; ++q) acc[i][j][q] = 0.f;

    auto issue = [&](int kt, int s) {
        int kg = kB + kt * BK;
        uint32_t base = (uint32_t)__cvta_generic_to_shared(plane(s, 0));
        #pragma unroll
        for (int v = 0; v < 2; ++v) {
            int idx  = tid + v * 256;
            int row  = idx >> 4;
            int c16  = idx & 15;
            uint32_t so = row * (AP * 2) + c16 * 16;
            size_t   aoff = (size_t)(kg + row) * M + m0 + c16 * 8;
            size_t   boff = (size_t)(kg + row) * N + n0 + c16 * 8;
            cpasync16(base + 0 * STG * 2 + so, Ahg + aoff);
            cpasync16(base + 1 * STG * 2 + so, Alg + aoff);
            cpasync16(base + 2 * STG * 2 + so, Bhg + boff);
            cpasync16(base + 3 * STG * 2 + so, Blg + boff);
        }
        asm volatile("cp.async.commit_group;");
    };

    const int aRow = (lane & 7) + ((lane >> 4) & 1) * 8;
    const int aCol = wm + ((lane >> 3) & 1) * 8;
    const int bRow = (lane & 7) + ((lane >> 3) & 1) * 8;
    const int bCol = wn + ((lane >> 4) & 1) * 8;

    // register-lean compute: B frags live across mi loop; A frags per-mi only
    auto compute = [&](int s) {
        uint32_t ahB = (uint32_t)__cvta_generic_to_shared(plane(s, 0));
        uint32_t alB = (uint32_t)__cvta_generic_to_shared(plane(s, 1));
        uint32_t bhB = (uint32_t)__cvta_generic_to_shared(plane(s, 2));
        uint32_t blB = (uint32_t)__cvta_generic_to_shared(plane(s, 3));
        #pragma unroll
        for (int k16 = 0; k16 < 2; ++k16) {
            int k0 = k16 * 16;
            uint32_t bhf[4][2], blf[4][2];
            #pragma unroll
            for (int p = 0; p < 2; ++p) {
                uint32_t off = ((k0 + bRow) * AP + bCol + p * 16) * 2;
                uint32_t r0, r1, r2, r3;
                ldsm_x4_t(r0, r1, r2, r3, bhB + off);
                bhf[2 * p][0] = r0; bhf[2 * p][1] = r1;
                bhf[2 * p + 1][0] = r2; bhf[2 * p + 1][1] = r3;
                ldsm_x4_t(r0, r1, r2, r3, blB + off);
                blf[2 * p][0] = r0; blf[2 * p][1] = r1;
                blf[2 * p + 1][0] = r2; blf[2 * p + 1][1] = r3;
            }
            #pragma unroll
            for (int mi = 0; mi < 4; ++mi) {
                uint32_t ahf[4], alf[4];
                uint32_t off = ((k0 + aRow) * AP + aCol + mi * 16) * 2;
                ldsm_x4_t(ahf[0], ahf[1], ahf[2], ahf[3], ahB + off);
                ldsm_x4_t(alf[0], alf[1], alf[2], alf[3], alB + off);
                #pragma unroll
                for (int ni = 0; ni < 4; ++ni) {
                    mma16816(acc[mi][ni], ahf, bhf[ni]);
                    mma16816(acc[mi][ni], ahf, blf[ni]);
                    mma16816(acc[mi][ni], alf, bhf[ni]);
                }
            }
        }
    };

    issue(0, 0);
    for (int kt = 0; kt < KT; ++kt) {
        if (kt + 1 < KT) {
            issue(kt + 1, (kt + 1) & 1);
            asm volatile("cp.async.wait_group 1;");
        } else {
            asm volatile("cp.async.wait_group 0;");
        }
        __syncthreads();
        compute(kt & 1);
        __syncthreads();
    }

    float* Cp = Cpart + (size_t)blockIdx.z * M * N;
    const int rB = m0 + wm + (lane >> 2);
    const int cB = n0 + wn + (lane & 3) * 2;
    #pragma unroll
    for (int mi = 0; mi < 4; ++mi)
        #pragma unroll
        for (int ni = 0; ni < 4; ++ni) {
            int r = rB + mi * 16;
            int c = cB + ni * 8;
            *reinterpret_cast<float2*>(Cp + (size_t)r * N + c) =
                make_float2(acc[mi][ni][0], acc[mi][ni][1]);
            *reinterpret_cast<float2*>(Cp + (size_t)(r + 8) * N + c) =
                make_float2(acc[mi][ni][2], acc[mi][ni][3]);
        }
}

// ---------------------------------------------------------------------------
template<int SPLITK, bool RELU>
__global__ void reduce_epi_kernel(const float* __restrict__ part,
                                  const float* __restrict__ bias,
                                  float* __restrict__ C, int N)
{
    int i4 = blockIdx.x * blockDim.x + threadIdx.x;
    int MN4 = N_NODES * N / 4;
    if (i4 >= MN4) return;
    const float4* p = reinterpret_cast<const float4*>(part);
    float4 s = p[i4];
    #pragma unroll
    for (int sp = 1; sp < SPLITK; ++sp) {
        float4 v = p[i4 + (size_t)sp * MN4];
        s.x += v.x; s.y += v.y; s.z += v.z; s.w += v.w;
    }
    int row = (i4 * 4) / N;
    int col = (i4 * 4) % N;
    float sc = g_dis[row];
    float4 bb = *reinterpret_cast<const float4*>(bias + col);
    float4 r;
    r.x = s.x * sc + bb.x;
    r.y = s.y * sc + bb.y;
    r.z = s.z * sc + bb.z;
    r.w = s.w * sc + bb.w;
    if (RELU) {
        r.x = fmaxf(r.x, 0.f); r.y = fmaxf(r.y, 0.f);
        r.z = fmaxf(r.z, 0.f); r.w = fmaxf(r.w, 0.f);
    }
    reinterpret_cast<float4*>(C)[i4] = r;
}

// ---------------------------------------------------------------------------
// SIMT fp32 GEMM; epilogue writes bf16 hi/lo planes.
// ---------------------------------------------------------------------------
template<int BM, int BN, int BK, int TM, int TN, bool GATHER_A>
__global__ __launch_bounds__((BM / TM) * (BN / TN))
void simt_gemm(const float* __restrict__ A, int lda,
               const float* __restrict__ B,
               __nv_bfloat16* __restrict__ Ch,
               __nv_bfloat16* __restrict__ Cl,
               float* __restrict__ Cf,
               const float* __restrict__ rowScale,
               const int* __restrict__ gatherIdx,
               int M, int N, int K)
{
    constexpr int NT   = (BM / TM) * (BN / TN);
    constexpr int APAD = 4;
    constexpr int AV   = (BM * BK) / (4 * NT);
    constexpr int BV   = (BK * BN) / (4 * NT);

    __shared__ float As[BK][BM + APAD];
    __shared__ float Bs[BK][BN];

    const int tid = threadIdx.x;
    const int tx  = tid % (BN / TN);
    const int ty  = tid / (BN / TN);
    const int m0  = blockIdx.y * BM;
    const int n0  = blockIdx.x * BN;

    float4 areg[AV], breg[BV];
    float acc[TM][TN];
    #pragma unroll
    for (int i = 0; i < TM; ++i)
        #pragma unroll
        for (int j = 0; j < TN; ++j) acc[i][j] = 0.f;

    auto loadA = [&](int k0) {
        #pragma unroll
        for (int v = 0; v < AV; ++v) {
            int idx = tid + v * NT;
            int m  = idx / (BK / 4);
            int kq = idx % (BK / 4);
            int row = GATHER_A ? gatherIdx[m0 + m] : (m0 + m);
            areg[v] = *reinterpret_cast<const float4*>(A + (size_t)row * lda + (k0 + kq * 4));
        }
    };
    auto storeA = [&]() {
        #pragma unroll
        for (int v = 0; v < AV; ++v) {
            int idx = tid + v * NT;
            int m  = idx / (BK / 4);
            int kq = idx % (BK / 4);
            As[kq * 4 + 0][m] = areg[v].x;
            As[kq * 4 + 1][m] = areg[v].y;
            As[kq * 4 + 2][m] = areg[v].z;
            As[kq * 4 + 3][m] = areg[v].w;
        }
    };
    auto loadB = [&](int k0) {
        #pragma unroll
        for (int v = 0; v < BV; ++v) {
            int idx = tid + v * NT;
            int k  = idx / (BN / 4);
            int n4 = idx % (BN / 4);
            breg[v] = *reinterpret_cast<const float4*>(B + (size_t)(k0 + k) * N + (n0 + n4 * 4));
        }
    };
    auto storeB = [&]() {
        #pragma unroll
        for (int v = 0; v < BV; ++v) {
            int idx = tid + v * NT;
            int k  = idx / (BN / 4);
            int n4 = idx % (BN / 4);
            *reinterpret_cast<float4*>(&Bs[k][n4 * 4]) = breg[v];
        }
    };

    loadA(0); loadB(0);
    storeA(); storeB();
    __syncthreads();

    const int KT = K / BK;
    for (int kt = 0; kt < KT; ++kt) {
        if (kt + 1 < KT) { loadA((kt + 1) * BK); loadB((kt + 1) * BK); }
        #pragma unroll
        for (int kk = 0; kk < BK; ++kk) {
            float a[TM], b[TN];
            #pragma unroll
            for (int i = 0; i < TM; i += 4) {
                float4 t = *reinterpret_cast<const float4*>(&As[kk][ty * TM + i]);
                a[i] = t.x; a[i + 1] = t.y; a[i + 2] = t.z; a[i + 3] = t.w;
            }
            #pragma unroll
            for (int j = 0; j < TN; j += 4) {
                float4 t = *reinterpret_cast<const float4*>(&Bs[kk][tx * TN + j]);
                b[j] = t.x; b[j + 1] = t.y; b[j + 2] = t.z; b[j + 3] = t.w;
            }
            #pragma unroll
            for (int i = 0; i < TM; ++i)
                #pragma unroll
                for (int j = 0; j < TN; ++j)
                    acc[i][j] = fmaf(a[i], b[j], acc[i][j]);
        }
        if (kt + 1 < KT) {
            __syncthreads();
            storeA(); storeB();
            __syncthreads();
        }
    }

    #pragma unroll
    for (int i = 0; i < TM; ++i) {
        int row = m0 + ty * TM + i;
        float sc = rowScale[row];
        #pragma unroll
        for (int j = 0; j < TN; j += 4) {
            int col = n0 + tx * TN + j;
            float x0 = acc[i][j + 0] * sc;
            float x1 = acc[i][j + 1] * sc;
            float x2 = acc[i][j + 2] * sc;
            float x3 = acc[i][j + 3] * sc;
            uint2 h, l;
            h.x = packbf2(x0, x1);
            h.y = packbf2(x2, x3);
            l.x = packbf2(x0 - bf16of(x0), x1 - bf16of(x1));
            l.y = packbf2(x2 - bf16of(x2), x3 - bf16of(x3));
            size_t off = ((size_t)row * N + col) / 4;
            reinterpret_cast<uint2*>(Ch)[off] = h;
            reinterpret_cast<uint2*>(Cl)[off] = l;
            if (Cf) {
                *reinterpret_cast<float4*>(Cf + (size_t)row * N + col) =
                    make_float4(x0, x1, x2, x3);
            }
        }
    }
}

// ---------------------------------------------------------------------------
// decode: bucket sort by src, then block-per-src with smem-cached z[src]
// ---------------------------------------------------------------------------
__global__ void zero_cnt_kernel()
{
    int i = blockIdx.x * blockDim.x + threadIdx.x;
    if (i < N_NODES) g_cnt[i] = 0;
}

__global__ void hist_kernel(const int* __restrict__ eli, int nPred)
{
    int i = blockIdx.x * blockDim.x + threadIdx.x;
    if (i < nPred) atomicAdd(&g_cnt[eli[i]], 1);
}

__global__ __launch_bounds__(1024)
void scan_kernel()
{
    __shared__ int part[1024];
    const int tid = threadIdx.x;
    int loc[8];
    int s = 0;
    #pragma unroll
    for (int j = 0; j < 8; ++j) {
        loc[j] = g_cnt[tid * 8 + j];
        s += loc[j];
    }
    part[tid] = s;
    __syncthreads();
    for (int off = 1; off < 1024; off <<= 1) {
        int v = (tid >= off) ? part[tid - off] : 0;
        __syncthreads();
        part[tid] += v;
        __syncthreads();
    }
    int run = part[tid] - s;      // exclusive
    #pragma unroll
    for (int j = 0; j < 8; ++j) {
        g_start[tid * 8 + j] = run;
        g_cur[tid * 8 + j]   = run;
        run += loc[j];
    }
    if (tid == 1023) g_start[N_NODES] = run;
}

__global__ void scatter_kernel(const int* __restrict__ eli, int nPred)
{
    int i = blockIdx.x * blockDim.x + threadIdx.x;
    if (i >= nPred) return;
    int s = eli[i];
    int pos = atomicAdd(&g_cur[s], 1);
    g_sdst[pos] = eli[nPred + i];
    g_seid[pos] = i;
}

__global__ __launch_bounds__(256)
void decode_sorted_kernel(float* __restrict__ out)
{
    __shared__ float zsrc[OUT_C];
    const int b   = blockIdx.x;               // src node
    const int tid = threadIdx.x;
    if (tid < OUT_C) zsrc[tid] = g_Z[(size_t)b * OUT_C + tid];
    __syncthreads();
    const int s0 = g_start[b];
    const int s1 = g_start[b + 1];
    const int lane = tid & 31;
    const int w    = tid >> 5;
    const float4 av = reinterpret_cast<const float4*>(zsrc)[lane];
    for (int e = s0 + w; e < s1; e += 8) {
        int d = g_sdst[e];
        float4 bv = reinterpret_cast<const float4*>(g_Z + (size_t)d * OUT_C)[lane];
        float dot = av.x * bv.x + av.y * bv.y + av.z * bv.z + av.w * bv.w;
        #pragma unroll
        for (int o = 16; o; o >>= 1) dot += __shfl_xor_sync(0xffffffffu, dot, o);
        if (lane == 0) out[g_seid[e]] = dot;
    }
}

// ---------------------------------------------------------------------------
extern "C" void kernel_launch(void* const* d_in, const int* in_sizes, int n_in,
                              void* d_out, int out_size)
{
    const int*   nodeIdx = (const int*)  d_in[0];
    const float* attn    = (const float*)d_in[1];
    const int*   eli     = (const int*)  d_in[2];
    const float* emb     = (const float*)d_in[3];
    const float* W1      = (const float*)d_in[4];
    const float* b1      = (const float*)d_in[5];
    const float* W2      = (const float*)d_in[6];
    const float* b2      = (const float*)d_in[7];
    float* out = (float*)d_out;
    const int nPred = in_sizes[2] / 2;

    float *pDis, *pH, *pZ, *pPart;
    __nv_bfloat16 *pAh, *pAl, *pBh, *pBl;
    cudaGetSymbolAddress((void**)&pDis,  g_dis);
    cudaGetSymbolAddress((void**)&pH,    g_H);
    cudaGetSymbolAddress((void**)&pZ,    g_Z);
    cudaGetSymbolAddress((void**)&pPart, g_part);
    cudaGetSymbolAddress((void**)&pAh,   g_Ah);
    cudaGetSymbolAddress((void**)&pAl,   g_Al);
    cudaGetSymbolAddress((void**)&pBh,   g_Bh);
    cudaGetSymbolAddress((void**)&pBl,   g_Bl);

    constexpr int TC_SMEM = 2 * 4 * 32 * 136 * 2;   // 69632 B
    cudaFuncSetAttribute(tc_gemm<2>, cudaFuncAttributeMaxDynamicSharedMemorySize, TC_SMEM);
    cudaFuncSetAttribute(tc_gemm<4>, cudaFuncAttributeMaxDynamicSharedMemorySize, TC_SMEM);

    // 0) edge bucket sort (independent of GEMM chain; runs up front)
    zero_cnt_kernel<<<N_NODES / 256, 256>>>();
    hist_kernel<<<(nPred + 255) / 256, 256>>>(eli, nPred);
    scan_kernel<<<1, 1024>>>();
    scatter_kernel<<<(nPred + 255) / 256, 256>>>(eli, nPred);

    // 1) convert + deg (fused), then dis
    convert_deg_kernel<<<dim3(8, 64), 256>>>(attn);
    dis_kernel<<<N_NODES / 256, 256>>>();

    // 2) P (bf16 hi/lo) = dis ⊙ (emb[nodeIdx] @ W1)
    simt_gemm<128, 64, 16, 8, 8, true>
        <<<dim3(HID_C / 64, N_NODES / 128), 128>>>(
            emb, E_DIM_C, W1, pBh, pBl, nullptr, pDis, nodeIdx, N_NODES, HID_C, E_DIM_C);

    // 3) H partials = w^T @ P   split-K=2 (TC)
    tc_gemm<2><<<dim3(HID_C / 128, N_NODES / 128, 2), 256, TC_SMEM>>>(
        pAh, pAl, pBh, pBl, pPart, N_NODES, HID_C, N_NODES);
    reduce_epi_kernel<2, true>
        <<<(N_NODES * HID_C / 4 + 255) / 256, 256>>>(pPart, b1, pH, HID_C);

    // 4) Q (bf16 hi/lo) = dis ⊙ (H @ W2)
    simt_gemm<128, 64, 16, 8, 8, false>
        <<<dim3(OUT_C / 64, N_NODES / 128), 128>>>(
            pH, HID_C, W2, pBh, pBl, nullptr, pDis, nullptr, N_NODES, OUT_C, HID_C);

    // 5) Z partials = w^T @ Q   split-K=4 (TC)
    tc_gemm<4><<<dim3(OUT_C / 128, N_NODES / 128, 4), 256, TC_SMEM>>>(
        pAh, pAl, pBh, pBl, pPart, N_NODES, OUT_C, N_NODES);
    reduce_epi_kernel<4, false>
        <<<(N_NODES * OUT_C / 4 + 255) / 256, 256>>>(pPart, b2, pZ, OUT_C);

    // 6) decode (block per src node, z[src] cached in smem)
    decode_sorted_kernel<<<N_NODES, 256>>>(out);
}